// round 5
// baseline (speedup 1.0000x reference)
#include <cuda_runtime.h>
#include <cuda_fp16.h>
#include <stdint.h>

#define NN   50000
#define EE   800000
#define HDIM 256
#define LDIM 128
#define BN_EPS 1e-5f
#define SCAN_B 196          // ceil(NN/256)
#define KP2  40             // padded BK stride in halves (32+8)

// ---------------- scratch (static device globals; no allocation) ----------------
__device__ float  g_dinv[NN];
__device__ int    g_cnt [NN];
__device__ int    g_ptr [NN];
__device__ int    g_pos [NN];
__device__ int    g_bsum[256];
__device__ int    g_boff[256];
__device__ int2   g_csr [EE];                    // x=src, y=coef bits
__device__ __half g_h16[(size_t)NN * HDIM];      // GEMM out (agg in)
__device__ __half g_a16[(size_t)NN * HDIM];      // agg out (next GEMM in)
__device__ float  g_stats[2 * HDIM];             // col sum / sumsq
__device__ float  g_ss   [2 * HDIM];             // scale / shift
__device__ __half g_w0t[HDIM * HDIM];            // W0^T  [n][k]
__device__ __half g_w1t[HDIM * HDIM];            // W1^T  [n][k]
__device__ __half g_wct[HDIM * HDIM];            // [Wmu|Wlv]^T [n][k], n<128 = mu
__device__ float  g_bcat[HDIM];                  // [bmu|blv]

// ---------------- helpers ----------------
__device__ __forceinline__ void mma_f16(float* c, const uint32_t* a,
                                        uint32_t b0, uint32_t b1) {
    asm volatile(
        "mma.sync.aligned.m16n8k16.row.col.f32.f16.f16.f32 "
        "{%0,%1,%2,%3}, {%4,%5,%6,%7}, {%8,%9}, {%0,%1,%2,%3};\n"
        : "+f"(c[0]), "+f"(c[1]), "+f"(c[2]), "+f"(c[3])
        : "r"(a[0]), "r"(a[1]), "r"(a[2]), "r"(a[3]), "r"(b0), "r"(b1));
}

// ---------------- graph preprocessing ----------------
__global__ void k_cnt_zero() {
    int i = blockIdx.x * blockDim.x + threadIdx.x;
    if (i < NN) g_cnt[i] = 0;
}

__global__ void k_cnt(const int* __restrict__ dst) {
    int e = blockIdx.x * blockDim.x + threadIdx.x;
    if (e < EE) atomicAdd(&g_cnt[dst[e]], 1);
}

// dinv + zero stats + convert/transpose weights to fp16 [n][k] + combined head bias
__global__ void k_dinv_wcvt(const float* __restrict__ W0, const float* __restrict__ W1,
                            const float* __restrict__ Wmu, const float* __restrict__ Wlv,
                            const float* __restrict__ bmu, const float* __restrict__ blv) {
    int b = blockIdx.x;
    if (b < SCAN_B) {
        int i = b * 256 + threadIdx.x;
        if (i < NN) g_dinv[i] = rsqrtf((float)g_cnt[i] + 1.0f);
        if (b == 0 && threadIdx.x < 2 * HDIM) g_stats[threadIdx.x] = 0.0f;
        return;
    }
    if (b == SCAN_B) {
        int t = threadIdx.x;
        g_bcat[t] = (t < 128) ? bmu[t] : blv[t - 128];
    }
    int idx = (b - SCAN_B) * 256 + threadIdx.x;      // 0 .. 196607
    if (idx < 65536) {
        int n = idx >> 8, k = idx & 255;
        g_w0t[idx] = __float2half(W0[k * 256 + n]);
    } else if (idx < 131072) {
        int j = idx - 65536; int n = j >> 8, k = j & 255;
        g_w1t[j] = __float2half(W1[k * 256 + n]);
    } else if (idx < 196608) {
        int j = idx - 131072; int n = j >> 8, k = j & 255;
        float v = (n < 128) ? Wmu[k * 128 + n] : Wlv[k * 128 + (n - 128)];
        g_wct[j] = __float2half(v);
    }
}

__global__ void k_bsum() {
    __shared__ int sm[256];
    int t = threadIdx.x;
    int i = blockIdx.x * 256 + t;
    sm[t] = (i < NN) ? g_cnt[i] : 0;
    __syncthreads();
    for (int off = 128; off > 0; off >>= 1) {
        if (t < off) sm[t] += sm[t + off];
        __syncthreads();
    }
    if (t == 0) g_bsum[blockIdx.x] = sm[0];
}

__global__ void k_bscan() {
    __shared__ int sm[256];
    int t = threadIdx.x;
    int v = (t < SCAN_B) ? g_bsum[t] : 0;
    sm[t] = v;
    __syncthreads();
    for (int off = 1; off < 256; off <<= 1) {
        int u = (t >= off) ? sm[t - off] : 0;
        __syncthreads();
        sm[t] += u;
        __syncthreads();
    }
    g_boff[t] = sm[t] - v;
}

__global__ void k_ptr() {
    __shared__ int sm[256];
    int t = threadIdx.x;
    int i = blockIdx.x * 256 + t;
    int c = (i < NN) ? g_cnt[i] : 0;
    sm[t] = c;
    __syncthreads();
    for (int off = 1; off < 256; off <<= 1) {
        int u = (t >= off) ? sm[t - off] : 0;
        __syncthreads();
        sm[t] += u;
        __syncthreads();
    }
    if (i < NN) {
        int p = g_boff[blockIdx.x] + sm[t] - c;
        g_ptr[i] = p;
        g_pos[i] = p;
    }
}

__global__ void k_fill(const int* __restrict__ src, const int* __restrict__ dst) {
    int e = blockIdx.x * blockDim.x + threadIdx.x;
    if (e >= EE) return;
    int s = src[e], d = dst[e];
    int p = atomicAdd(&g_pos[d], 1);
    float c = g_dinv[s] * g_dinv[d];
    g_csr[p] = make_int2(s, __float_as_int(c));
}

// ---------------- pipelined fp16 tensor-core GEMM ----------------
// C[M,256-wide] = act(A)[M,256] @ Wt^T, Wt fp16 [n][k]. BM=128 BN=128 BK=32,
// 256 threads = 8 warps (4m x 2n), warp tile 32x64. 2-stage smem double buffer.
// A16: A is fp16 (else fp32). FUSE_BN: relu(v*ss[k]+ss[256+k]) at A load.
// OUT16: write fp16 C (stride 256). SPLIT: fp32 out, col<128 -> mu, else logvar.
template <bool A16, bool FUSE_BN, bool OUT16, bool SPLIT>
__global__ void __launch_bounds__(256)
gemm_p(const void* __restrict__ Av, const __half* __restrict__ Wt,
       const float* __restrict__ bias, float* __restrict__ Cf,
       __half* __restrict__ Ch, int M) {
    __shared__ __half As[2][128 * KP2];
    __shared__ __half Bs[2][128 * KP2];

    const float*  A32 = (const float*)Av;
    const __half* Ah  = (const __half*)Av;

    int tid  = threadIdx.x;
    int wid  = tid >> 5, lane = tid & 31;
    int g    = lane >> 2, tg = lane & 3;
    int mb   = (wid & 3) * 32;
    int nb   = (wid >> 2) * 64;
    int rowBase = blockIdx.x * 128;
    int colBase = blockIdx.y * 128;

    float acc[2][8][4] = {};
    float4 arf[4];
    uint4  arh[2];
    uint4  brr[2];

    // ---- staging helpers ----
    auto ldg_stage = [&](int t) {
        int k0 = t * 32;
        if (A16) {
#pragma unroll
            for (int i = 0; i < 2; i++) {
                int idx = tid + i * 256;             // 0..511
                int r = idx >> 2, c8 = (idx & 3) << 3;
                int gr = rowBase + r;
                uint4 v = make_uint4(0u, 0u, 0u, 0u);
                if (gr < M) v = *(const uint4*)&Ah[(size_t)gr * 256 + k0 + c8];
                arh[i] = v;
            }
        } else {
#pragma unroll
            for (int i = 0; i < 4; i++) {
                int idx = tid + i * 256;             // 0..1023
                int r = idx >> 3, c4 = (idx & 7) << 2;
                int gr = rowBase + r;
                float4 v = make_float4(0.f, 0.f, 0.f, 0.f);
                if (gr < M) v = *(const float4*)&A32[(size_t)gr * 256 + k0 + c4];
                arf[i] = v;
            }
        }
#pragma unroll
        for (int i = 0; i < 2; i++) {
            int idx = tid + i * 256;
            int n = idx >> 2, c8 = (idx & 3) << 3;
            brr[i] = *(const uint4*)&Wt[(size_t)(colBase + n) * 256 + k0 + c8];
        }
    };

    auto sts_stage = [&](int st, int t) {
        int k0 = t * 32;
        if (A16) {
#pragma unroll
            for (int i = 0; i < 2; i++) {
                int idx = tid + i * 256;
                int r = idx >> 2, c8 = (idx & 3) << 3;
                uint4 v = arh[i];
                if (FUSE_BN) {
                    uint32_t* w = (uint32_t*)&v;
#pragma unroll
                    for (int j = 0; j < 4; j++) {
                        float2 p = __half22float2(*(__half2*)&w[j]);
                        int kf = k0 + c8 + j * 2;
                        float2 sc = *(const float2*)&g_ss[kf];
                        float2 sh = *(const float2*)&g_ss[256 + kf];
                        p.x = fmaxf(p.x * sc.x + sh.x, 0.0f);
                        p.y = fmaxf(p.y * sc.y + sh.y, 0.0f);
                        __half2 h = __floats2half2_rn(p.x, p.y);
                        w[j] = *(uint32_t*)&h;
                    }
                }
                *(uint4*)&As[st][r * KP2 + c8] = v;
            }
        } else {
#pragma unroll
            for (int i = 0; i < 4; i++) {
                int idx = tid + i * 256;
                int r = idx >> 3, c4 = (idx & 7) << 2;
                float4 v = arf[i];
                __half2 h0 = __floats2half2_rn(v.x, v.y);
                __half2 h1 = __floats2half2_rn(v.z, v.w);
                uint2 o = make_uint2(*(uint32_t*)&h0, *(uint32_t*)&h1);
                *(uint2*)&As[st][r * KP2 + c4] = o;
            }
        }
#pragma unroll
        for (int i = 0; i < 2; i++) {
            int idx = tid + i * 256;
            int n = idx >> 2, c8 = (idx & 3) << 3;
            *(uint4*)&Bs[st][n * KP2 + c8] = brr[i];
        }
    };

    // ---- prologue ----
    ldg_stage(0);
    sts_stage(0, 0);
    __syncthreads();

    // ---- main loop: 8 K-steps of 32, double buffered ----
#pragma unroll
    for (int t = 0; t < 8; t++) {
        if (t < 7) ldg_stage(t + 1);

        int st = t & 1;
        uint32_t AsB = (uint32_t)__cvta_generic_to_shared(&As[st][0]);
#pragma unroll
        for (int ks = 0; ks < 2; ks++) {
            int kk = ks * 16;
            uint32_t a[2][4];
#pragma unroll
            for (int im = 0; im < 2; im++) {
                int row = mb + im * 16 + (lane & 15);
                int col = kk + ((lane >> 4) << 3);
                uint32_t addr = AsB + (uint32_t)(row * KP2 + col) * 2u;
                asm volatile(
                    "ldmatrix.sync.aligned.m8n8.x4.shared.b16 {%0,%1,%2,%3}, [%4];"
                    : "=r"(a[im][0]), "=r"(a[im][1]), "=r"(a[im][2]), "=r"(a[im][3])
                    : "r"(addr));
            }
#pragma unroll
            for (int nt = 0; nt < 8; nt++) {
                const __half* bp = &Bs[st][(nb + nt * 8 + g) * KP2 + kk + 2 * tg];
                uint32_t b0 = *(const uint32_t*)bp;
                uint32_t b1 = *(const uint32_t*)(bp + 8);
                mma_f16(acc[0][nt], a[0], b0, b1);
                mma_f16(acc[1][nt], a[1], b0, b1);
            }
        }

        if (t < 7) {
            sts_stage((t + 1) & 1, t + 1);
            __syncthreads();
        }
    }

    // ---- epilogue ----
#pragma unroll
    for (int im = 0; im < 2; im++) {
#pragma unroll
        for (int nt = 0; nt < 8; nt++) {
            int row0 = rowBase + mb + im * 16 + g;
            int col  = colBase + nb + nt * 8 + tg * 2;
            float bx = 0.f, by = 0.f;
            if (bias) { bx = bias[col]; by = bias[col + 1]; }
#pragma unroll
            for (int h = 0; h < 2; h++) {
                int row = row0 + h * 8;
                if (row < M) {
                    float ox = acc[im][nt][h * 2 + 0] + bx;
                    float oy = acc[im][nt][h * 2 + 1] + by;
                    if (OUT16) {
                        *(__half2*)&Ch[(size_t)row * 256 + col] =
                            __floats2half2_rn(ox, oy);
                    } else if (SPLIT) {
                        if (col < 128)
                            *(float2*)&Cf[(size_t)row * 128 + col] =
                                make_float2(ox, oy);
                        else
                            *(float2*)&Cf[(size_t)NN * 128 + (size_t)row * 128 + (col - 128)] =
                                make_float2(ox, oy);
                    }
                }
            }
        }
    }
}

// ---------------- CSR aggregation + fused BN stats (fp16 in/out) ----------------
__global__ void k_agg_csr(const __half* __restrict__ h, __half* __restrict__ out,
                          const float* __restrict__ bias) {
    __shared__ float s_sum[4][256];
    __shared__ float s_sq [4][256];

    int grp  = threadIdx.x >> 6;
    int lane = threadIdx.x & 63;
    int node = blockIdx.x * 4 + grp;
    int f = lane * 4;

    float4 acc = make_float4(0.f, 0.f, 0.f, 0.f);
    if (node < NN) {
        float di = g_dinv[node];
        float cs = di * di;
        uint2 raw = *(const uint2*)&h[(size_t)node * 256 + f];
        float2 v01 = __half22float2(*(__half2*)&raw.x);
        float2 v23 = __half22float2(*(__half2*)&raw.y);
        float4 b = *(const float4*)&bias[f];
        acc.x = v01.x * cs + b.x;
        acc.y = v01.y * cs + b.y;
        acc.z = v23.x * cs + b.z;
        acc.w = v23.y * cs + b.w;

        int beg = g_ptr[node];
        int end = beg + g_cnt[node];
        if (beg < end) {
            int2 rec = g_csr[beg];
            for (int j = beg; j < end; j++) {
                int   s = rec.x;
                float c = __int_as_float(rec.y);
                uint2 r2 = *(const uint2*)&h[(size_t)s * 256 + f];
                if (j + 1 < end) rec = g_csr[j + 1];
                float2 w01 = __half22float2(*(__half2*)&r2.x);
                float2 w23 = __half22float2(*(__half2*)&r2.y);
                acc.x += c * w01.x; acc.y += c * w01.y;
                acc.z += c * w23.x; acc.w += c * w23.y;
            }
        }
        __half2 o01 = __floats2half2_rn(acc.x, acc.y);
        __half2 o23 = __floats2half2_rn(acc.z, acc.w);
        uint2 ov = make_uint2(*(uint32_t*)&o01, *(uint32_t*)&o23);
        *(uint2*)&out[(size_t)node * 256 + f] = ov;
    }

    s_sum[grp][f + 0] = acc.x; s_sum[grp][f + 1] = acc.y;
    s_sum[grp][f + 2] = acc.z; s_sum[grp][f + 3] = acc.w;
    s_sq [grp][f + 0] = acc.x * acc.x; s_sq[grp][f + 1] = acc.y * acc.y;
    s_sq [grp][f + 2] = acc.z * acc.z; s_sq[grp][f + 3] = acc.w * acc.w;
    __syncthreads();

    int t = threadIdx.x;
    float s = s_sum[0][t] + s_sum[1][t] + s_sum[2][t] + s_sum[3][t];
    float q = s_sq [0][t] + s_sq [1][t] + s_sq [2][t] + s_sq [3][t];
    atomicAdd(&g_stats[t], s);
    atomicAdd(&g_stats[HDIM + t], q);
}

__global__ void k_bn_final(const float* __restrict__ gamma, const float* __restrict__ beta) {
    int f = threadIdx.x;
    float inv_n = 1.0f / (float)NN;
    float m  = g_stats[f] * inv_n;
    float v  = g_stats[HDIM + f] * inv_n - m * m;
    float sc = gamma[f] * rsqrtf(v + BN_EPS);
    g_ss[f]        = sc;
    g_ss[HDIM + f] = beta[f] - m * sc;
    g_stats[f] = 0.0f;
    g_stats[HDIM + f] = 0.0f;
}

// ---------------- launch ----------------
extern "C" void kernel_launch(void* const* d_in, const int* in_sizes, int n_in,
                              void* d_out, int out_size) {
    const float* x   = (const float*)d_in[0];
    const int*   ei  = (const int*)  d_in[1];   // [2, E]: src then dst
    const float* W0  = (const float*)d_in[2];
    const float* b0  = (const float*)d_in[3];
    const float* g0  = (const float*)d_in[4];
    const float* be0 = (const float*)d_in[5];
    const float* W1  = (const float*)d_in[6];
    const float* b1  = (const float*)d_in[7];
    const float* g1  = (const float*)d_in[8];
    const float* be1 = (const float*)d_in[9];
    const float* Wmu = (const float*)d_in[10];
    const float* bmu = (const float*)d_in[11];
    const float* Wlv = (const float*)d_in[12];
    const float* blv = (const float*)d_in[13];
    float* out = (float*)d_out;

    const int* src = ei;
    const int* dst = ei + EE;

    __half *h16 = nullptr, *a16 = nullptr, *w0t = nullptr, *w1t = nullptr, *wct = nullptr;
    float  *bcat = nullptr;
    cudaGetSymbolAddress((void**)&h16,  g_h16);
    cudaGetSymbolAddress((void**)&a16,  g_a16);
    cudaGetSymbolAddress((void**)&w0t,  g_w0t);
    cudaGetSymbolAddress((void**)&w1t,  g_w1t);
    cudaGetSymbolAddress((void**)&wct,  g_wct);
    cudaGetSymbolAddress((void**)&bcat, g_bcat);

    const int NB_N  = SCAN_B;
    const int NB_E  = (EE + 255) / 256;
    const int NB_AG = (NN + 3) / 4;
    const int NB_DW = SCAN_B + 768;
    const dim3 G_GEMM((NN + 127) / 128, 2);     // 391 x 2, all GEMMs 256-wide

    // 1-3: counts, dinv + weight transpose/convert
    k_cnt_zero  <<<NB_N, 256>>>();
    k_cnt       <<<NB_E, 256>>>(dst);
    k_dinv_wcvt <<<NB_DW, 256>>>(W0, W1, Wmu, Wlv, bmu, blv);

    // 4: layer-0 hidden GEMM (profiled launch)
    gemm_p<false, false, true, false><<<G_GEMM, 256>>>(x, w0t, nullptr, nullptr, h16, NN);

    // 5-8: CSR build
    k_bsum <<<SCAN_B, 256>>>();
    k_bscan<<<1, 256>>>();
    k_ptr  <<<SCAN_B, 256>>>();
    k_fill <<<NB_E, 256>>>(src, dst);

    // layer 0 aggregation + BN coeffs
    k_agg_csr <<<NB_AG, 256>>>(h16, a16, b0);
    k_bn_final<<<1, 256>>>(g0, be0);

    // layer 1
    gemm_p<true, true, true, false><<<G_GEMM, 256>>>(a16, w1t, nullptr, nullptr, h16, NN);
    k_agg_csr <<<NB_AG, 256>>>(h16, a16, b1);
    k_bn_final<<<1, 256>>>(g1, be1);

    // heads: combined mu|logvar GEMM with split epilogue
    gemm_p<true, true, false, true><<<G_GEMM, 256>>>(a16, wct, bcat, out, nullptr, NN);
}

// round 6
// speedup vs baseline: 1.4488x; 1.4488x over previous
#include <cuda_runtime.h>
#include <cuda_fp16.h>
#include <stdint.h>

#define NN   50000
#define EE   800000
#define HDIM 256
#define LDIM 128
#define BN_EPS 1e-5f
#define SCAN_B 196          // ceil(NN/256)
#define KP2  40             // padded BK stride in halves (32+8) -> 80B rows, 16B aligned

// ---------------- scratch (static device globals; no allocation) ----------------
__device__ float  g_dinv[NN];
__device__ int    g_cnt [NN];
__device__ int    g_ptr [NN];
__device__ int    g_pos [NN];
__device__ int    g_bsum[256];
__device__ int    g_boff[256];
__device__ int2   g_csr [EE];                    // x=src, y=coef bits
__device__ __half g_h16[(size_t)NN * HDIM];      // GEMM out (agg in)
__device__ __half g_a16[(size_t)NN * HDIM];      // x16 / agg out (GEMM in)
__device__ float  g_stats[2 * HDIM];             // col sum / sumsq
__device__ float  g_ss   [2 * HDIM];             // scale / shift
__device__ __half g_w0t[HDIM * HDIM];            // W0^T  [n][k]
__device__ __half g_w1t[HDIM * HDIM];            // W1^T  [n][k]
__device__ __half g_wct[HDIM * HDIM];            // [Wmu|Wlv]^T [n][k]
__device__ float  g_bcat[HDIM];                  // [bmu|blv]

// ---------------- helpers ----------------
__device__ __forceinline__ void mma_f16(float* c, const uint32_t* a,
                                        uint32_t b0, uint32_t b1) {
    asm volatile(
        "mma.sync.aligned.m16n8k16.row.col.f32.f16.f16.f32 "
        "{%0,%1,%2,%3}, {%4,%5,%6,%7}, {%8,%9}, {%0,%1,%2,%3};\n"
        : "+f"(c[0]), "+f"(c[1]), "+f"(c[2]), "+f"(c[3])
        : "r"(a[0]), "r"(a[1]), "r"(a[2]), "r"(a[3]), "r"(b0), "r"(b1));
}

__device__ __forceinline__ void cp16(uint32_t dst_smem, const void* src) {
    asm volatile("cp.async.cg.shared.global [%0], [%1], 16;\n"
                 :: "r"(dst_smem), "l"(src));
}

__device__ __forceinline__ uint32_t bnfrag(uint32_t v, float2 sc, float2 sh) {
    float2 p = __half22float2(*(__half2*)&v);
    p.x = fmaxf(fmaf(p.x, sc.x, sh.x), 0.0f);
    p.y = fmaxf(fmaf(p.y, sc.y, sh.y), 0.0f);
    __half2 h = __floats2half2_rn(p.x, p.y);
    return *(uint32_t*)&h;
}

// ---------------- graph preprocessing ----------------
__global__ void k_cnt_zero() {
    int i = blockIdx.x * blockDim.x + threadIdx.x;
    if (i < NN) g_cnt[i] = 0;
}

__global__ void k_cnt(const int* __restrict__ dst) {
    int e = blockIdx.x * blockDim.x + threadIdx.x;
    if (e < EE) atomicAdd(&g_cnt[dst[e]], 1);
}

// dinv + zero stats + fp16 weight transpose + head bias + x -> fp16 (into g_a16)
__global__ void k_dinv_wcvt(const float* __restrict__ x,
                            const float* __restrict__ W0, const float* __restrict__ W1,
                            const float* __restrict__ Wmu, const float* __restrict__ Wlv,
                            const float* __restrict__ bmu, const float* __restrict__ blv) {
    int b = blockIdx.x;
    if (b < SCAN_B) {
        int i = b * 256 + threadIdx.x;
        if (i < NN) g_dinv[i] = rsqrtf((float)g_cnt[i] + 1.0f);
        if (b == 0 && threadIdx.x < 2 * HDIM) g_stats[threadIdx.x] = 0.0f;
        return;
    }
    if (b >= SCAN_B + 768) {                    // x conversion: 6250 blocks
        size_t j = (size_t)(b - (SCAN_B + 768)) * 2048 + (size_t)threadIdx.x * 8;
        float4 v0 = *(const float4*)&x[j];
        float4 v1 = *(const float4*)&x[j + 4];
        __half2 h0 = __floats2half2_rn(v0.x, v0.y);
        __half2 h1 = __floats2half2_rn(v0.z, v0.w);
        __half2 h2 = __floats2half2_rn(v1.x, v1.y);
        __half2 h3 = __floats2half2_rn(v1.z, v1.w);
        uint4 o = make_uint4(*(uint32_t*)&h0, *(uint32_t*)&h1,
                             *(uint32_t*)&h2, *(uint32_t*)&h3);
        *(uint4*)&g_a16[j] = o;
        return;
    }
    if (b == SCAN_B) {
        int t = threadIdx.x;
        g_bcat[t] = (t < 128) ? bmu[t] : blv[t - 128];
    }
    int idx = (b - SCAN_B) * 256 + threadIdx.x;      // 0 .. 196607
    if (idx < 65536) {
        int n = idx >> 8, k = idx & 255;
        g_w0t[idx] = __float2half(W0[k * 256 + n]);
    } else if (idx < 131072) {
        int j = idx - 65536; int n = j >> 8, k = j & 255;
        g_w1t[j] = __float2half(W1[k * 256 + n]);
    } else if (idx < 196608) {
        int j = idx - 131072; int n = j >> 8, k = j & 255;
        float v = (n < 128) ? Wmu[k * 128 + n] : Wlv[k * 128 + (n - 128)];
        g_wct[j] = __float2half(v);
    }
}

__global__ void k_bsum() {
    __shared__ int sm[256];
    int t = threadIdx.x;
    int i = blockIdx.x * 256 + t;
    sm[t] = (i < NN) ? g_cnt[i] : 0;
    __syncthreads();
    for (int off = 128; off > 0; off >>= 1) {
        if (t < off) sm[t] += sm[t + off];
        __syncthreads();
    }
    if (t == 0) g_bsum[blockIdx.x] = sm[0];
}

__global__ void k_bscan() {
    __shared__ int sm[256];
    int t = threadIdx.x;
    int v = (t < SCAN_B) ? g_bsum[t] : 0;
    sm[t] = v;
    __syncthreads();
    for (int off = 1; off < 256; off <<= 1) {
        int u = (t >= off) ? sm[t - off] : 0;
        __syncthreads();
        sm[t] += u;
        __syncthreads();
    }
    g_boff[t] = sm[t] - v;
}

__global__ void k_ptr() {
    __shared__ int sm[256];
    int t = threadIdx.x;
    int i = blockIdx.x * 256 + t;
    int c = (i < NN) ? g_cnt[i] : 0;
    sm[t] = c;
    __syncthreads();
    for (int off = 1; off < 256; off <<= 1) {
        int u = (t >= off) ? sm[t - off] : 0;
        __syncthreads();
        sm[t] += u;
        __syncthreads();
    }
    if (i < NN) {
        int p = g_boff[blockIdx.x] + sm[t] - c;
        g_ptr[i] = p;
        g_pos[i] = p;
    }
}

__global__ void k_fill(const int* __restrict__ src, const int* __restrict__ dst) {
    int e = blockIdx.x * blockDim.x + threadIdx.x;
    if (e >= EE) return;
    int s = src[e], d = dst[e];
    int p = atomicAdd(&g_pos[d], 1);
    float c = g_dinv[s] * g_dinv[d];
    g_csr[p] = make_int2(s, __float_as_int(c));
}

// ---------------- cp.async pipelined fp16 GEMM ----------------
// C[M,256] = act(A16)[M,256] @ Wt^T. BM=128 BN=128 BK=32, 256 thr = 8 warps
// (4m x 2n), warp tile 32x64. 3-stage cp.async pipeline, BN on A-fragments.
// OUT16: fp16 C (stride 256). else SPLIT fp32: col<128 -> mu, else logvar.
#define STG_H (128 * KP2)               // halves per (A or B) stage
template <bool FUSE_BN, bool OUT16>
__global__ void __launch_bounds__(256, 2)
gemm_ca(const __half* __restrict__ Ah, const __half* __restrict__ Wt,
        const float* __restrict__ bias, float* __restrict__ Cf,
        __half* __restrict__ Ch, int M) {
    extern __shared__ __half sm[];
    // stage s: A at sm + s*2*STG_H, B at +STG_H

    int tid  = threadIdx.x;
    int wid  = tid >> 5, lane = tid & 31;
    int g    = lane >> 2, tg = lane & 3;
    int mb   = (wid & 3) * 32;
    int nb   = (wid >> 2) * 64;
    int rowBase = blockIdx.x * 128;
    int colBase = blockIdx.y * 128;

    uint32_t smBase = (uint32_t)__cvta_generic_to_shared(sm);

    // A: 512 16B chunks (idx: r = idx>>2, c8 = (idx&3)*8); B likewise
    int aIdx = tid, r_a = aIdx >> 2, c8_a = (aIdx & 3) << 3;
    int gr  = rowBase + r_a;       int gr2  = (gr  < M) ? gr  : M - 1;
    int gr_b = rowBase + r_a + 64; int gr2b = (gr_b < M) ? gr_b : M - 1;

    auto load_stage = [&](int st, int t) {
        int k0 = t * 32;
        uint32_t aBase = smBase + (uint32_t)(st * 2 * STG_H) * 2u;
        uint32_t bBase = aBase + (uint32_t)STG_H * 2u;
        // A rows r_a and r_a+64
        cp16(aBase + (uint32_t)(r_a * KP2 + c8_a) * 2u,
             &Ah[(size_t)gr2 * 256 + k0 + c8_a]);
        cp16(aBase + (uint32_t)((r_a + 64) * KP2 + c8_a) * 2u,
             &Ah[(size_t)gr2b * 256 + k0 + c8_a]);
        // B rows n and n+64
        cp16(bBase + (uint32_t)(r_a * KP2 + c8_a) * 2u,
             &Wt[(size_t)(colBase + r_a) * 256 + k0 + c8_a]);
        cp16(bBase + (uint32_t)((r_a + 64) * KP2 + c8_a) * 2u,
             &Wt[(size_t)(colBase + r_a + 64) * 256 + k0 + c8_a]);
        asm volatile("cp.async.commit_group;\n" ::: "memory");
    };

    float acc[2][8][4] = {};

    // prologue: stages 0 and 1 in flight
    load_stage(0, 0);
    load_stage(1, 1);

#pragma unroll
    for (int t = 0; t < 8; t++) {
        if (t < 7) asm volatile("cp.async.wait_group 1;\n" ::: "memory");
        else       asm volatile("cp.async.wait_group 0;\n" ::: "memory");
        __syncthreads();
        if (t + 2 < 8) load_stage((t + 2) % 3, t + 2);

        int st = t % 3;
        uint32_t aBase = smBase + (uint32_t)(st * 2 * STG_H) * 2u;
        const __half* smB = sm + st * 2 * STG_H + STG_H;
        int k0 = t * 32;

#pragma unroll
        for (int ks = 0; ks < 2; ks++) {
            int kk = ks * 16;
            uint32_t a[2][4];
#pragma unroll
            for (int im = 0; im < 2; im++) {
                int row = mb + im * 16 + (lane & 15);
                int col = kk + ((lane >> 4) << 3);
                uint32_t addr = aBase + (uint32_t)(row * KP2 + col) * 2u;
                asm volatile(
                    "ldmatrix.sync.aligned.m8n8.x4.shared.b16 {%0,%1,%2,%3}, [%4];"
                    : "=r"(a[im][0]), "=r"(a[im][1]), "=r"(a[im][2]), "=r"(a[im][3])
                    : "r"(addr));
            }
            if (FUSE_BN) {
                int kb = k0 + kk + tg * 2;
                float2 sA = *(const float2*)&g_ss[kb];
                float2 hA = *(const float2*)&g_ss[256 + kb];
                float2 sB = *(const float2*)&g_ss[kb + 8];
                float2 hB = *(const float2*)&g_ss[256 + kb + 8];
#pragma unroll
                for (int im = 0; im < 2; im++) {
                    a[im][0] = bnfrag(a[im][0], sA, hA);
                    a[im][1] = bnfrag(a[im][1], sA, hA);
                    a[im][2] = bnfrag(a[im][2], sB, hB);
                    a[im][3] = bnfrag(a[im][3], sB, hB);
                }
            }
#pragma unroll
            for (int nt = 0; nt < 8; nt++) {
                const __half* bp = &smB[(nb + nt * 8 + g) * KP2 + kk + 2 * tg];
                uint32_t b0 = *(const uint32_t*)bp;
                uint32_t b1 = *(const uint32_t*)(bp + 8);
                mma_f16(acc[0][nt], a[0], b0, b1);
                mma_f16(acc[1][nt], a[1], b0, b1);
            }
        }
        __syncthreads();
    }

    // ---- epilogue ----
#pragma unroll
    for (int im = 0; im < 2; im++) {
#pragma unroll
        for (int nt = 0; nt < 8; nt++) {
            int row0 = rowBase + mb + im * 16 + g;
            int col  = colBase + nb + nt * 8 + tg * 2;
            float bx = 0.f, by = 0.f;
            if (bias) { bx = bias[col]; by = bias[col + 1]; }
#pragma unroll
            for (int h = 0; h < 2; h++) {
                int row = row0 + h * 8;
                if (row < M) {
                    float ox = acc[im][nt][h * 2 + 0] + bx;
                    float oy = acc[im][nt][h * 2 + 1] + by;
                    if (OUT16) {
                        *(__half2*)&Ch[(size_t)row * 256 + col] =
                            __floats2half2_rn(ox, oy);
                    } else {
                        if (col < 128)
                            *(float2*)&Cf[(size_t)row * 128 + col] =
                                make_float2(ox, oy);
                        else
                            *(float2*)&Cf[(size_t)NN * 128 + (size_t)row * 128 + (col - 128)] =
                                make_float2(ox, oy);
                    }
                }
            }
        }
    }
}

// ---------------- CSR aggregation, MLP=4, + fused BN stats ----------------
// 1 warp per node (8 halves/lane), 8 nodes per 256-thread block.
__device__ __forceinline__ void fma8(float* acc, uint4 r, float c) {
    __half2* hp = (__half2*)&r;
#pragma unroll
    for (int q = 0; q < 4; q++) {
        float2 p = __half22float2(hp[q]);
        acc[q * 2]     += c * p.x;
        acc[q * 2 + 1] += c * p.y;
    }
}

__global__ void k_agg_csr(const __half* __restrict__ h, __half* __restrict__ out,
                          const float* __restrict__ bias) {
    __shared__ float s_sum[8][256];
    __shared__ float s_sq [8][256];

    int grp  = threadIdx.x >> 5;     // 0..7
    int lane = threadIdx.x & 31;
    int node = blockIdx.x * 8 + grp;
    int f = lane * 8;

    float acc[8] = {};
    if (node < NN) {
        float di = g_dinv[node];
        float cs = di * di;
        // bias + self loop
#pragma unroll
        for (int q = 0; q < 8; q++) acc[q] = bias[f + q];
        fma8(acc, *(const uint4*)&h[(size_t)node * 256 + f], cs);

        int beg = g_ptr[node];
        int end = beg + g_cnt[node];
        int2 rec = make_int2(0, 0);
        if (lane < 4 && beg + lane < end) rec = g_csr[beg + lane];

        for (int j = beg; j < end; j += 4) {
            int2 cur = rec;
            int jn = j + 4;
            int2 nx = make_int2(0, 0);
            if (lane < 4 && jn + lane < end) nx = g_csr[jn + lane];
            rec = nx;
            int take = end - j;      // warp-uniform

            int   s0 = __shfl_sync(0xffffffffu, cur.x, 0);
            float c0 = __int_as_float(__shfl_sync(0xffffffffu, cur.y, 0));
            int   s1 = __shfl_sync(0xffffffffu, cur.x, 1);
            float c1 = __int_as_float(__shfl_sync(0xffffffffu, cur.y, 1));
            int   s2 = __shfl_sync(0xffffffffu, cur.x, 2);
            float c2 = __int_as_float(__shfl_sync(0xffffffffu, cur.y, 2));
            int   s3 = __shfl_sync(0xffffffffu, cur.x, 3);
            float c3 = __int_as_float(__shfl_sync(0xffffffffu, cur.y, 3));

            uint4 r0 = *(const uint4*)&h[(size_t)s0 * 256 + f];
            if (take > 1) {
                uint4 r1 = *(const uint4*)&h[(size_t)s1 * 256 + f];
                if (take > 2) {
                    uint4 r2 = *(const uint4*)&h[(size_t)s2 * 256 + f];
                    if (take > 3) {
                        uint4 r3 = *(const uint4*)&h[(size_t)s3 * 256 + f];
                        fma8(acc, r3, c3);
                    }
                    fma8(acc, r2, c2);
                }
                fma8(acc, r1, c1);
            }
            fma8(acc, r0, c0);
        }

        __half2 o0 = __floats2half2_rn(acc[0], acc[1]);
        __half2 o1 = __floats2half2_rn(acc[2], acc[3]);
        __half2 o2 = __floats2half2_rn(acc[4], acc[5]);
        __half2 o3 = __floats2half2_rn(acc[6], acc[7]);
        uint4 ov = make_uint4(*(uint32_t*)&o0, *(uint32_t*)&o1,
                              *(uint32_t*)&o2, *(uint32_t*)&o3);
        *(uint4*)&out[(size_t)node * 256 + f] = ov;
    }

#pragma unroll
    for (int q = 0; q < 8; q++) {
        s_sum[grp][f + q] = acc[q];
        s_sq [grp][f + q] = acc[q] * acc[q];
    }
    __syncthreads();

    int t = threadIdx.x;   // feature
    float s = 0.f, q = 0.f;
#pragma unroll
    for (int gi = 0; gi < 8; gi++) { s += s_sum[gi][t]; q += s_sq[gi][t]; }
    atomicAdd(&g_stats[t], s);
    atomicAdd(&g_stats[HDIM + t], q);
}

__global__ void k_bn_final(const float* __restrict__ gamma, const float* __restrict__ beta) {
    int f = threadIdx.x;
    float inv_n = 1.0f / (float)NN;
    float m  = g_stats[f] * inv_n;
    float v  = g_stats[HDIM + f] * inv_n - m * m;
    float sc = gamma[f] * rsqrtf(v + BN_EPS);
    g_ss[f]        = sc;
    g_ss[HDIM + f] = beta[f] - m * sc;
    g_stats[f] = 0.0f;
    g_stats[HDIM + f] = 0.0f;
}

// ---------------- launch ----------------
extern "C" void kernel_launch(void* const* d_in, const int* in_sizes, int n_in,
                              void* d_out, int out_size) {
    const float* x   = (const float*)d_in[0];
    const int*   ei  = (const int*)  d_in[1];   // [2, E]: src then dst
    const float* W0  = (const float*)d_in[2];
    const float* b0  = (const float*)d_in[3];
    const float* g0  = (const float*)d_in[4];
    const float* be0 = (const float*)d_in[5];
    const float* W1  = (const float*)d_in[6];
    const float* b1  = (const float*)d_in[7];
    const float* g1  = (const float*)d_in[8];
    const float* be1 = (const float*)d_in[9];
    const float* Wmu = (const float*)d_in[10];
    const float* bmu = (const float*)d_in[11];
    const float* Wlv = (const float*)d_in[12];
    const float* blv = (const float*)d_in[13];
    float* out = (float*)d_out;

    const int* src = ei;
    const int* dst = ei + EE;

    __half *h16 = nullptr, *a16 = nullptr, *w0t = nullptr, *w1t = nullptr, *wct = nullptr;
    float  *bcat = nullptr;
    cudaGetSymbolAddress((void**)&h16,  g_h16);
    cudaGetSymbolAddress((void**)&a16,  g_a16);
    cudaGetSymbolAddress((void**)&w0t,  g_w0t);
    cudaGetSymbolAddress((void**)&w1t,  g_w1t);
    cudaGetSymbolAddress((void**)&wct,  g_wct);
    cudaGetSymbolAddress((void**)&bcat, g_bcat);

    const int NB_N  = SCAN_B;
    const int NB_E  = (EE + 255) / 256;
    const int NB_AG = (NN + 7) / 8;             // 6250
    const int NB_DW = SCAN_B + 768 + 6250;      // dinv + weights + x-convert
    const dim3 G_GEMM((NN + 127) / 128, 2);     // 391 x 2

    const int SMEM = 3 * 2 * STG_H * 2;         // 61440 bytes
    cudaFuncSetAttribute(gemm_ca<false, true>,
                         cudaFuncAttributeMaxDynamicSharedMemorySize, SMEM);
    cudaFuncSetAttribute(gemm_ca<true, true>,
                         cudaFuncAttributeMaxDynamicSharedMemorySize, SMEM);
    cudaFuncSetAttribute(gemm_ca<true, false>,
                         cudaFuncAttributeMaxDynamicSharedMemorySize, SMEM);

    // 1-3: counts, dinv + weight cvt + x -> fp16 (into a16)
    k_cnt_zero  <<<NB_N, 256>>>();
    k_cnt       <<<NB_E, 256>>>(dst);
    k_dinv_wcvt <<<NB_DW, 256>>>(x, W0, W1, Wmu, Wlv, bmu, blv);

    // 4: layer-0 hidden GEMM (profiled launch)
    gemm_ca<false, true><<<G_GEMM, 256, SMEM>>>(a16, w0t, nullptr, nullptr, h16, NN);

    // 5-8: CSR build
    k_bsum <<<SCAN_B, 256>>>();
    k_bscan<<<1, 256>>>();
    k_ptr  <<<SCAN_B, 256>>>();
    k_fill <<<NB_E, 256>>>(src, dst);

    // layer 0 aggregation + BN coeffs
    k_agg_csr <<<NB_AG, 256>>>(h16, a16, b0);
    k_bn_final<<<1, 256>>>(g0, be0);

    // layer 1
    gemm_ca<true, true><<<G_GEMM, 256, SMEM>>>(a16, w1t, nullptr, nullptr, h16, NN);
    k_agg_csr <<<NB_AG, 256>>>(h16, a16, b1);
    k_bn_final<<<1, 256>>>(g1, be1);

    // heads: combined mu|logvar GEMM with split epilogue
    gemm_ca<true, false><<<G_GEMM, 256, SMEM>>>(a16, wct, bcat, out, nullptr, NN);
}

// round 7
// speedup vs baseline: 1.4758x; 1.0187x over previous
#include <cuda_runtime.h>
#include <cuda_fp16.h>
#include <stdint.h>

#define NN   50000
#define EE   800000
#define HDIM 256
#define LDIM 128
#define BN_EPS 1e-5f
#define SCAN_B 196          // ceil(NN/256)
#define KP2  40             // padded BK stride in halves (32+8) -> conflict-free ldmatrix

// ---------------- scratch (static device globals; no allocation) ----------------
__device__ float  g_dinv[NN];
__device__ int    g_cnt [NN];
__device__ int    g_ptr [NN];
__device__ int    g_pos [NN];
__device__ int    g_bsum[256];
__device__ int    g_boff[256];
__device__ int2   g_csr [EE];                    // x=src, y=coef bits
__device__ __half g_h16[(size_t)NN * HDIM];      // GEMM out (agg in)
__device__ __half g_a16[(size_t)NN * HDIM];      // x16 / agg out (GEMM in)
__device__ float  g_stats[2 * HDIM];             // col sum / sumsq
__device__ float  g_ss   [2 * HDIM];             // scale / shift
__device__ __half g_w0t[HDIM * HDIM];            // W0^T  [n][k]
__device__ __half g_w1t[HDIM * HDIM];            // W1^T  [n][k]
__device__ __half g_wct[HDIM * HDIM];            // [Wmu|Wlv]^T [n][k]
__device__ float  g_bcat[HDIM];                  // [bmu|blv]

// ---------------- helpers ----------------
__device__ __forceinline__ void mma_f16(float* c, const uint32_t* a,
                                        uint32_t b0, uint32_t b1) {
    asm volatile(
        "mma.sync.aligned.m16n8k16.row.col.f32.f16.f16.f32 "
        "{%0,%1,%2,%3}, {%4,%5,%6,%7}, {%8,%9}, {%0,%1,%2,%3};\n"
        : "+f"(c[0]), "+f"(c[1]), "+f"(c[2]), "+f"(c[3])
        : "r"(a[0]), "r"(a[1]), "r"(a[2]), "r"(a[3]), "r"(b0), "r"(b1));
}

__device__ __forceinline__ void cp16(uint32_t dst_smem, const void* src) {
    asm volatile("cp.async.cg.shared.global [%0], [%1], 16;\n"
                 :: "r"(dst_smem), "l"(src));
}

__device__ __forceinline__ uint32_t bnfrag(uint32_t v, float2 sc, float2 sh) {
    float2 p = __half22float2(*(__half2*)&v);
    p.x = fmaxf(fmaf(p.x, sc.x, sh.x), 0.0f);
    p.y = fmaxf(fmaf(p.y, sc.y, sh.y), 0.0f);
    __half2 h = __floats2half2_rn(p.x, p.y);
    return *(uint32_t*)&h;
}

// ---------------- graph preprocessing ----------------
__global__ void k_cnt_zero() {
    int i = blockIdx.x * blockDim.x + threadIdx.x;
    if (i < NN) g_cnt[i] = 0;
}

__global__ void k_cnt(const int* __restrict__ dst) {
    int e = blockIdx.x * blockDim.x + threadIdx.x;
    if (e < EE) atomicAdd(&g_cnt[dst[e]], 1);
}

// dinv + zero stats + fp16 weight transpose + head bias + x -> fp16 (into g_a16)
__global__ void k_dinv_wcvt(const float* __restrict__ x,
                            const float* __restrict__ W0, const float* __restrict__ W1,
                            const float* __restrict__ Wmu, const float* __restrict__ Wlv,
                            const float* __restrict__ bmu, const float* __restrict__ blv) {
    int b = blockIdx.x;
    if (b < SCAN_B) {
        int i = b * 256 + threadIdx.x;
        if (i < NN) g_dinv[i] = rsqrtf((float)g_cnt[i] + 1.0f);
        if (b == 0 && threadIdx.x < 2 * HDIM) g_stats[threadIdx.x] = 0.0f;
        return;
    }
    if (b >= SCAN_B + 768) {                    // x conversion: 6250 blocks
        size_t j = (size_t)(b - (SCAN_B + 768)) * 2048 + (size_t)threadIdx.x * 8;
        float4 v0 = *(const float4*)&x[j];
        float4 v1 = *(const float4*)&x[j + 4];
        __half2 h0 = __floats2half2_rn(v0.x, v0.y);
        __half2 h1 = __floats2half2_rn(v0.z, v0.w);
        __half2 h2 = __floats2half2_rn(v1.x, v1.y);
        __half2 h3 = __floats2half2_rn(v1.z, v1.w);
        uint4 o = make_uint4(*(uint32_t*)&h0, *(uint32_t*)&h1,
                             *(uint32_t*)&h2, *(uint32_t*)&h3);
        *(uint4*)&g_a16[j] = o;
        return;
    }
    if (b == SCAN_B) {
        int t = threadIdx.x;
        g_bcat[t] = (t < 128) ? bmu[t] : blv[t - 128];
    }
    int idx = (b - SCAN_B) * 256 + threadIdx.x;      // 0 .. 196607
    if (idx < 65536) {
        int n = idx >> 8, k = idx & 255;
        g_w0t[idx] = __float2half(W0[k * 256 + n]);
    } else if (idx < 131072) {
        int j = idx - 65536; int n = j >> 8, k = j & 255;
        g_w1t[j] = __float2half(W1[k * 256 + n]);
    } else if (idx < 196608) {
        int j = idx - 131072; int n = j >> 8, k = j & 255;
        float v = (n < 128) ? Wmu[k * 128 + n] : Wlv[k * 128 + (n - 128)];
        g_wct[j] = __float2half(v);
    }
}

__global__ void k_bsum() {
    __shared__ int sm[256];
    int t = threadIdx.x;
    int i = blockIdx.x * 256 + t;
    sm[t] = (i < NN) ? g_cnt[i] : 0;
    __syncthreads();
    for (int off = 128; off > 0; off >>= 1) {
        if (t < off) sm[t] += sm[t + off];
        __syncthreads();
    }
    if (t == 0) g_bsum[blockIdx.x] = sm[0];
}

__global__ void k_bscan() {
    __shared__ int sm[256];
    int t = threadIdx.x;
    int v = (t < SCAN_B) ? g_bsum[t] : 0;
    sm[t] = v;
    __syncthreads();
    for (int off = 1; off < 256; off <<= 1) {
        int u = (t >= off) ? sm[t - off] : 0;
        __syncthreads();
        sm[t] += u;
        __syncthreads();
    }
    g_boff[t] = sm[t] - v;
}

__global__ void k_ptr() {
    __shared__ int sm[256];
    int t = threadIdx.x;
    int i = blockIdx.x * 256 + t;
    int c = (i < NN) ? g_cnt[i] : 0;
    sm[t] = c;
    __syncthreads();
    for (int off = 1; off < 256; off <<= 1) {
        int u = (t >= off) ? sm[t - off] : 0;
        __syncthreads();
        sm[t] += u;
        __syncthreads();
    }
    if (i < NN) {
        int p = g_boff[blockIdx.x] + sm[t] - c;
        g_ptr[i] = p;
        g_pos[i] = p;
    }
}

__global__ void k_fill(const int* __restrict__ src, const int* __restrict__ dst) {
    int e = blockIdx.x * blockDim.x + threadIdx.x;
    if (e >= EE) return;
    int s = src[e], d = dst[e];
    int p = atomicAdd(&g_pos[d], 1);
    float c = g_dinv[s] * g_dinv[d];
    g_csr[p] = make_int2(s, __float_as_int(c));
}

// ---------------- cp.async pipelined fp16 GEMM ----------------
// C[M,256] = act(A16)[M,256] @ Wt^T. BM=128 BN=128 BK=32, 256 thr = 8 warps
// (4m x 2n), warp tile 32x64. 3-stage cp.async pipeline, BN on A-fragments,
// B fragments via ldmatrix.x4, single barrier per K-step.
#define STG_H (128 * KP2)               // halves per (A or B) stage
template <bool FUSE_BN, bool OUT16>
__global__ void __launch_bounds__(256, 2)
gemm_ca(const __half* __restrict__ Ah, const __half* __restrict__ Wt,
        const float* __restrict__ bias, float* __restrict__ Cf,
        __half* __restrict__ Ch, int M) {
    extern __shared__ __half sm[];

    int tid  = threadIdx.x;
    int wid  = tid >> 5, lane = tid & 31;
    int g    = lane >> 2, tg = lane & 3;
    int mb   = (wid & 3) * 32;
    int nb   = (wid >> 2) * 64;
    int rowBase = blockIdx.x * 128;
    int colBase = blockIdx.y * 128;

    uint32_t smBase = (uint32_t)__cvta_generic_to_shared(sm);

    int r_a = tid >> 2, c8_a = (tid & 3) << 3;
    int gr   = rowBase + r_a;       int gr2  = (gr   < M) ? gr   : M - 1;
    int gr_b = rowBase + r_a + 64;  int gr2b = (gr_b < M) ? gr_b : M - 1;

    auto load_stage = [&](int st, int t) {
        int k0 = t * 32;
        uint32_t aBase = smBase + (uint32_t)(st * 2 * STG_H) * 2u;
        uint32_t bBase = aBase + (uint32_t)STG_H * 2u;
        cp16(aBase + (uint32_t)(r_a * KP2 + c8_a) * 2u,
             &Ah[(size_t)gr2 * 256 + k0 + c8_a]);
        cp16(aBase + (uint32_t)((r_a + 64) * KP2 + c8_a) * 2u,
             &Ah[(size_t)gr2b * 256 + k0 + c8_a]);
        cp16(bBase + (uint32_t)(r_a * KP2 + c8_a) * 2u,
             &Wt[(size_t)(colBase + r_a) * 256 + k0 + c8_a]);
        cp16(bBase + (uint32_t)((r_a + 64) * KP2 + c8_a) * 2u,
             &Wt[(size_t)(colBase + r_a + 64) * 256 + k0 + c8_a]);
        asm volatile("cp.async.commit_group;\n" ::: "memory");
    };

    float acc[2][8][4] = {};

    // ldmatrix lane decomposition (shared by A and B loads)
    int lm  = lane >> 3;           // matrix index 0..3
    int lr  = lane & 7;            // row within matrix

    // prologue: stages 0 and 1 in flight
    load_stage(0, 0);
    load_stage(1, 1);

#pragma unroll
    for (int t = 0; t < 8; t++) {
        if (t < 7) asm volatile("cp.async.wait_group 1;\n" ::: "memory");
        else       asm volatile("cp.async.wait_group 0;\n" ::: "memory");
        __syncthreads();
        if (t + 2 < 8) load_stage((t + 2) % 3, t + 2);

        int st = t % 3;
        uint32_t aBase = smBase + (uint32_t)(st * 2 * STG_H) * 2u;
        uint32_t bBase = aBase + (uint32_t)STG_H * 2u;
        int k0 = t * 32;

#pragma unroll
        for (int ks = 0; ks < 2; ks++) {
            int kk = ks * 16;
            // A fragments: 2 x ldmatrix.x4
            uint32_t a[2][4];
#pragma unroll
            for (int im = 0; im < 2; im++) {
                int row = mb + im * 16 + (lane & 15);
                int col = kk + ((lane >> 4) << 3);
                uint32_t addr = aBase + (uint32_t)(row * KP2 + col) * 2u;
                asm volatile(
                    "ldmatrix.sync.aligned.m8n8.x4.shared.b16 {%0,%1,%2,%3}, [%4];"
                    : "=r"(a[im][0]), "=r"(a[im][1]), "=r"(a[im][2]), "=r"(a[im][3])
                    : "r"(addr));
            }
            if (FUSE_BN) {
                int kb = k0 + kk + tg * 2;
                float2 sA = *(const float2*)&g_ss[kb];
                float2 hA = *(const float2*)&g_ss[256 + kb];
                float2 sB = *(const float2*)&g_ss[kb + 8];
                float2 hB = *(const float2*)&g_ss[256 + kb + 8];
#pragma unroll
                for (int im = 0; im < 2; im++) {
                    a[im][0] = bnfrag(a[im][0], sA, hA);
                    a[im][1] = bnfrag(a[im][1], sA, hA);
                    a[im][2] = bnfrag(a[im][2], sB, hB);
                    a[im][3] = bnfrag(a[im][3], sB, hB);
                }
            }
            // B fragments: 4 x ldmatrix.x4 (non-trans; rows = n, cols = k)
            // matrix lm: n-offset = (lm>>1)*8, k-offset = (lm&1)*8
            uint32_t bf[8][2];
#pragma unroll
            for (int ntp = 0; ntp < 4; ntp++) {
                int row_n = nb + ntp * 16 + ((lm >> 1) << 3) + lr;
                int col   = kk + ((lm & 1) << 3);
                uint32_t addr = bBase + (uint32_t)(row_n * KP2 + col) * 2u;
                asm volatile(
                    "ldmatrix.sync.aligned.m8n8.x4.shared.b16 {%0,%1,%2,%3}, [%4];"
                    : "=r"(bf[ntp * 2][0]),     "=r"(bf[ntp * 2][1]),
                      "=r"(bf[ntp * 2 + 1][0]), "=r"(bf[ntp * 2 + 1][1])
                    : "r"(addr));
            }
#pragma unroll
            for (int nt = 0; nt < 8; nt++) {
                mma_f16(acc[0][nt], a[0], bf[nt][0], bf[nt][1]);
                mma_f16(acc[1][nt], a[1], bf[nt][0], bf[nt][1]);
            }
        }
    }

    // ---- epilogue ----
#pragma unroll
    for (int im = 0; im < 2; im++) {
#pragma unroll
        for (int nt = 0; nt < 8; nt++) {
            int row0 = rowBase + mb + im * 16 + g;
            int col  = colBase + nb + nt * 8 + tg * 2;
            float bx = 0.f, by = 0.f;
            if (bias) { bx = bias[col]; by = bias[col + 1]; }
#pragma unroll
            for (int h = 0; h < 2; h++) {
                int row = row0 + h * 8;
                if (row < M) {
                    float ox = acc[im][nt][h * 2 + 0] + bx;
                    float oy = acc[im][nt][h * 2 + 1] + by;
                    if (OUT16) {
                        *(__half2*)&Ch[(size_t)row * 256 + col] =
                            __floats2half2_rn(ox, oy);
                    } else {
                        if (col < 128)
                            *(float2*)&Cf[(size_t)row * 128 + col] =
                                make_float2(ox, oy);
                        else
                            *(float2*)&Cf[(size_t)NN * 128 + (size_t)row * 128 + (col - 128)] =
                                make_float2(ox, oy);
                    }
                }
            }
        }
    }
}

// ---------------- CSR aggregation, MLP=4, + fused BN stats ----------------
__device__ __forceinline__ void fma8(float* acc, uint4 r, float c) {
    __half2* hp = (__half2*)&r;
#pragma unroll
    for (int q = 0; q < 4; q++) {
        float2 p = __half22float2(hp[q]);
        acc[q * 2]     += c * p.x;
        acc[q * 2 + 1] += c * p.y;
    }
}

__global__ void k_agg_csr(const __half* __restrict__ h, __half* __restrict__ out,
                          const float* __restrict__ bias) {
    __shared__ float s_sum[8][256];
    __shared__ float s_sq [8][256];

    int grp  = threadIdx.x >> 5;     // 0..7
    int lane = threadIdx.x & 31;
    int node = blockIdx.x * 8 + grp;
    int f = lane * 8;

    float acc[8] = {};
    if (node < NN) {
        float di = g_dinv[node];
        float cs = di * di;
#pragma unroll
        for (int q = 0; q < 8; q++) acc[q] = bias[f + q];
        fma8(acc, *(const uint4*)&h[(size_t)node * 256 + f], cs);

        int beg = g_ptr[node];
        int end = beg + g_cnt[node];
        int2 rec = make_int2(0, 0);
        if (lane < 4 && beg + lane < end) rec = g_csr[beg + lane];

        for (int j = beg; j < end; j += 4) {
            int2 cur = rec;
            int jn = j + 4;
            int2 nx = make_int2(0, 0);
            if (lane < 4 && jn + lane < end) nx = g_csr[jn + lane];
            rec = nx;
            int take = end - j;      // warp-uniform

            int   s0 = __shfl_sync(0xffffffffu, cur.x, 0);
            float c0 = __int_as_float(__shfl_sync(0xffffffffu, cur.y, 0));
            int   s1 = __shfl_sync(0xffffffffu, cur.x, 1);
            float c1 = __int_as_float(__shfl_sync(0xffffffffu, cur.y, 1));
            int   s2 = __shfl_sync(0xffffffffu, cur.x, 2);
            float c2 = __int_as_float(__shfl_sync(0xffffffffu, cur.y, 2));
            int   s3 = __shfl_sync(0xffffffffu, cur.x, 3);
            float c3 = __int_as_float(__shfl_sync(0xffffffffu, cur.y, 3));

            uint4 r0 = *(const uint4*)&h[(size_t)s0 * 256 + f];
            if (take > 1) {
                uint4 r1 = *(const uint4*)&h[(size_t)s1 * 256 + f];
                if (take > 2) {
                    uint4 r2 = *(const uint4*)&h[(size_t)s2 * 256 + f];
                    if (take > 3) {
                        uint4 r3 = *(const uint4*)&h[(size_t)s3 * 256 + f];
                        fma8(acc, r3, c3);
                    }
                    fma8(acc, r2, c2);
                }
                fma8(acc, r1, c1);
            }
            fma8(acc, r0, c0);
        }

        __half2 o0 = __floats2half2_rn(acc[0], acc[1]);
        __half2 o1 = __floats2half2_rn(acc[2], acc[3]);
        __half2 o2 = __floats2half2_rn(acc[4], acc[5]);
        __half2 o3 = __floats2half2_rn(acc[6], acc[7]);
        uint4 ov = make_uint4(*(uint32_t*)&o0, *(uint32_t*)&o1,
                              *(uint32_t*)&o2, *(uint32_t*)&o3);
        *(uint4*)&out[(size_t)node * 256 + f] = ov;
    }

#pragma unroll
    for (int q = 0; q < 8; q++) {
        s_sum[grp][f + q] = acc[q];
        s_sq [grp][f + q] = acc[q] * acc[q];
    }
    __syncthreads();

    int t = threadIdx.x;   // feature
    float s = 0.f, q = 0.f;
#pragma unroll
    for (int gi = 0; gi < 8; gi++) { s += s_sum[gi][t]; q += s_sq[gi][t]; }
    atomicAdd(&g_stats[t], s);
    atomicAdd(&g_stats[HDIM + t], q);
}

__global__ void k_bn_final(const float* __restrict__ gamma, const float* __restrict__ beta) {
    int f = threadIdx.x;
    float inv_n = 1.0f / (float)NN;
    float m  = g_stats[f] * inv_n;
    float v  = g_stats[HDIM + f] * inv_n - m * m;
    float sc = gamma[f] * rsqrtf(v + BN_EPS);
    g_ss[f]        = sc;
    g_ss[HDIM + f] = beta[f] - m * sc;
    g_stats[f] = 0.0f;
    g_stats[HDIM + f] = 0.0f;
}

// ---------------- launch ----------------
extern "C" void kernel_launch(void* const* d_in, const int* in_sizes, int n_in,
                              void* d_out, int out_size) {
    const float* x   = (const float*)d_in[0];
    const int*   ei  = (const int*)  d_in[1];   // [2, E]: src then dst
    const float* W0  = (const float*)d_in[2];
    const float* b0  = (const float*)d_in[3];
    const float* g0  = (const float*)d_in[4];
    const float* be0 = (const float*)d_in[5];
    const float* W1  = (const float*)d_in[6];
    const float* b1  = (const float*)d_in[7];
    const float* g1  = (const float*)d_in[8];
    const float* be1 = (const float*)d_in[9];
    const float* Wmu = (const float*)d_in[10];
    const float* bmu = (const float*)d_in[11];
    const float* Wlv = (const float*)d_in[12];
    const float* blv = (const float*)d_in[13];
    float* out = (float*)d_out;

    const int* src = ei;
    const int* dst = ei + EE;

    __half *h16 = nullptr, *a16 = nullptr, *w0t = nullptr, *w1t = nullptr, *wct = nullptr;
    float  *bcat = nullptr;
    cudaGetSymbolAddress((void**)&h16,  g_h16);
    cudaGetSymbolAddress((void**)&a16,  g_a16);
    cudaGetSymbolAddress((void**)&w0t,  g_w0t);
    cudaGetSymbolAddress((void**)&w1t,  g_w1t);
    cudaGetSymbolAddress((void**)&wct,  g_wct);
    cudaGetSymbolAddress((void**)&bcat, g_bcat);

    const int NB_N  = SCAN_B;
    const int NB_E  = (EE + 255) / 256;
    const int NB_AG = (NN + 7) / 8;             // 6250
    const int NB_DW = SCAN_B + 768 + 6250;      // dinv + weights + x-convert
    const dim3 G_GEMM((NN + 127) / 128, 2);     // 391 x 2

    const int SMEM = 3 * 2 * STG_H * 2;         // 61440 bytes
    cudaFuncSetAttribute(gemm_ca<false, true>,
                         cudaFuncAttributeMaxDynamicSharedMemorySize, SMEM);
    cudaFuncSetAttribute(gemm_ca<true, true>,
                         cudaFuncAttributeMaxDynamicSharedMemorySize, SMEM);
    cudaFuncSetAttribute(gemm_ca<true, false>,
                         cudaFuncAttributeMaxDynamicSharedMemorySize, SMEM);

    // 1-3: counts, dinv + weight cvt + x -> fp16 (into a16)
    k_cnt_zero  <<<NB_N, 256>>>();
    k_cnt       <<<NB_E, 256>>>(dst);
    k_dinv_wcvt <<<NB_DW, 256>>>(x, W0, W1, Wmu, Wlv, bmu, blv);

    // 4: layer-0 hidden GEMM (profiled launch)
    gemm_ca<false, true><<<G_GEMM, 256, SMEM>>>(a16, w0t, nullptr, nullptr, h16, NN);

    // 5-8: CSR build
    k_bsum <<<SCAN_B, 256>>>();
    k_bscan<<<1, 256>>>();
    k_ptr  <<<SCAN_B, 256>>>();
    k_fill <<<NB_E, 256>>>(src, dst);

    // layer 0 aggregation + BN coeffs
    k_agg_csr <<<NB_AG, 256>>>(h16, a16, b0);
    k_bn_final<<<1, 256>>>(g0, be0);

    // layer 1
    gemm_ca<true, true><<<G_GEMM, 256, SMEM>>>(a16, w1t, nullptr, nullptr, h16, NN);
    k_agg_csr <<<NB_AG, 256>>>(h16, a16, b1);
    k_bn_final<<<1, 256>>>(g1, be1);

    // heads: combined mu|logvar GEMM with split epilogue
    gemm_ca<true, false><<<G_GEMM, 256, SMEM>>>(a16, wct, bcat, out, nullptr, NN);
}

// round 9
// speedup vs baseline: 1.5328x; 1.0386x over previous
#include <cuda_runtime.h>
#include <cuda_fp16.h>
#include <stdint.h>

#define NN   50000
#define EE   800000
#define HDIM 256
#define LDIM 128
#define BN_EPS 1e-5f
#define SCAN_B 196          // ceil(NN/256)
#define KP2  40             // padded BK stride in halves (32+8) -> conflict-free ldmatrix

// ---------------- scratch (static device globals; no allocation) ----------------
__device__ float  g_dinv[NN];
__device__ int    g_cnt [NN];
__device__ int    g_ptr [NN];
__device__ int    g_pos [NN];
__device__ int    g_total;
__device__ int2   g_csr [EE];                    // x=src, y=coef bits
__device__ __half g_h16[(size_t)NN * HDIM];      // GEMM out (agg in)
__device__ __half g_a16[(size_t)NN * HDIM];      // x16 / agg out (GEMM in)
__device__ float  g_stats[2 * HDIM];             // col sum / sumsq
__device__ float  g_ss   [2 * HDIM];             // scale / shift
__device__ __half g_w0t[HDIM * HDIM];            // W0^T  [n][k]
__device__ __half g_w1t[HDIM * HDIM];            // W1^T  [n][k]
__device__ __half g_wct[HDIM * HDIM];            // [Wmu|Wlv]^T [n][k]
__device__ float  g_bcat[HDIM];                  // [bmu|blv]

// ---------------- helpers ----------------
__device__ __forceinline__ void mma_f16(float* c, const uint32_t* a,
                                        uint32_t b0, uint32_t b1) {
    asm volatile(
        "mma.sync.aligned.m16n8k16.row.col.f32.f16.f16.f32 "
        "{%0,%1,%2,%3}, {%4,%5,%6,%7}, {%8,%9}, {%0,%1,%2,%3};\n"
        : "+f"(c[0]), "+f"(c[1]), "+f"(c[2]), "+f"(c[3])
        : "r"(a[0]), "r"(a[1]), "r"(a[2]), "r"(a[3]), "r"(b0), "r"(b1));
}

__device__ __forceinline__ void cp16(uint32_t dst_smem, const void* src) {
    asm volatile("cp.async.cg.shared.global [%0], [%1], 16;\n"
                 :: "r"(dst_smem), "l"(src));
}

__device__ __forceinline__ uint32_t bnfrag(uint32_t v, float2 sc, float2 sh) {
    float2 p = __half22float2(*(__half2*)&v);
    p.x = fmaxf(fmaf(p.x, sc.x, sh.x), 0.0f);
    p.y = fmaxf(fmaf(p.y, sc.y, sh.y), 0.0f);
    __half2 h = __floats2half2_rn(p.x, p.y);
    return *(uint32_t*)&h;
}

// ---------------- graph preprocessing ----------------
__global__ void k_cnt_zero() {
    int i = blockIdx.x * blockDim.x + threadIdx.x;
    if (i < NN) g_cnt[i] = 0;
    if (i == 0) g_total = 0;
}

__global__ void k_cnt(const int* __restrict__ dst) {
    int e = blockIdx.x * blockDim.x + threadIdx.x;
    if (e < EE) atomicAdd(&g_cnt[dst[e]], 1);
}

// dinv + zero stats + fp16 weight transpose + head bias + x -> fp16 (into g_a16)
__global__ void k_dinv_wcvt(const float* __restrict__ x,
                            const float* __restrict__ W0, const float* __restrict__ W1,
                            const float* __restrict__ Wmu, const float* __restrict__ Wlv,
                            const float* __restrict__ bmu, const float* __restrict__ blv) {
    int b = blockIdx.x;
    if (b < SCAN_B) {
        int i = b * 256 + threadIdx.x;
        if (i < NN) g_dinv[i] = rsqrtf((float)g_cnt[i] + 1.0f);
        if (b == 0 && threadIdx.x < 2 * HDIM) g_stats[threadIdx.x] = 0.0f;
        return;
    }
    if (b >= SCAN_B + 768) {                    // x conversion: 6250 blocks
        size_t j = (size_t)(b - (SCAN_B + 768)) * 2048 + (size_t)threadIdx.x * 8;
        float4 v0 = *(const float4*)&x[j];
        float4 v1 = *(const float4*)&x[j + 4];
        __half2 h0 = __floats2half2_rn(v0.x, v0.y);
        __half2 h1 = __floats2half2_rn(v0.z, v0.w);
        __half2 h2 = __floats2half2_rn(v1.x, v1.y);
        __half2 h3 = __floats2half2_rn(v1.z, v1.w);
        uint4 o = make_uint4(*(uint32_t*)&h0, *(uint32_t*)&h1,
                             *(uint32_t*)&h2, *(uint32_t*)&h3);
        *(uint4*)&g_a16[j] = o;
        return;
    }
    if (b == SCAN_B) {
        int t = threadIdx.x;
        g_bcat[t] = (t < 128) ? bmu[t] : blv[t - 128];
    }
    int idx = (b - SCAN_B) * 256 + threadIdx.x;      // 0 .. 196607
    if (idx < 65536) {
        int n = idx >> 8, k = idx & 255;
        g_w0t[idx] = __float2half(W0[k * 256 + n]);
    } else if (idx < 131072) {
        int j = idx - 65536; int n = j >> 8, k = j & 255;
        g_w1t[j] = __float2half(W1[k * 256 + n]);
    } else if (idx < 196608) {
        int j = idx - 131072; int n = j >> 8, k = j & 255;
        float v = (n < 128) ? Wmu[k * 128 + n] : Wlv[k * 128 + (n - 128)];
        g_wct[j] = __float2half(v);
    }
}

// CSR segment assignment: order-free atomic allocation (segments disjoint,
// node order irrelevant for correctness)
__global__ void k_ptra() {
    int i = blockIdx.x * blockDim.x + threadIdx.x;
    if (i < NN) {
        int c = g_cnt[i];
        int p = atomicAdd(&g_total, c);
        g_ptr[i] = p;
        g_pos[i] = p;
    }
}

__global__ void k_fill(const int* __restrict__ src, const int* __restrict__ dst) {
    int e = blockIdx.x * blockDim.x + threadIdx.x;
    if (e >= EE) return;
    int s = src[e], d = dst[e];
    int p = atomicAdd(&g_pos[d], 1);
    float c = g_dinv[s] * g_dinv[d];
    g_csr[p] = make_int2(s, __float_as_int(c));
}

// ---------------- cp.async pipelined fp16 GEMM (4-stage) ----------------
// C[M,256] = act(A16)[M,256] @ Wt^T. BM=128 BN=128 BK=32, 256 thr = 8 warps
// (4m x 2n), warp tile 32x64. 4-stage cp.async pipeline, BN on A-fragments,
// B fragments via ldmatrix.x4, single barrier per K-step.
#define STG_H (128 * KP2)               // halves per (A or B) stage
#define NSTG  4
template <bool FUSE_BN, bool OUT16>
__global__ void __launch_bounds__(256, 2)
gemm_ca(const __half* __restrict__ Ah, const __half* __restrict__ Wt,
        const float* __restrict__ bias, float* __restrict__ Cf,
        __half* __restrict__ Ch, int M) {
    extern __shared__ __half sm[];

    int tid  = threadIdx.x;
    int wid  = tid >> 5, lane = tid & 31;
    int g    = lane >> 2, tg = lane & 3;
    int mb   = (wid & 3) * 32;
    int nb   = (wid >> 2) * 64;
    int rowBase = blockIdx.x * 128;
    int colBase = blockIdx.y * 128;

    uint32_t smBase = (uint32_t)__cvta_generic_to_shared(sm);

    int r_a = tid >> 2, c8_a = (tid & 3) << 3;
    int gr   = rowBase + r_a;       int gr2  = (gr   < M) ? gr   : M - 1;
    int gr_b = rowBase + r_a + 64;  int gr2b = (gr_b < M) ? gr_b : M - 1;

    auto load_stage = [&](int st, int t) {
        int k0 = t * 32;
        uint32_t aBase = smBase + (uint32_t)(st * 2 * STG_H) * 2u;
        uint32_t bBase = aBase + (uint32_t)STG_H * 2u;
        cp16(aBase + (uint32_t)(r_a * KP2 + c8_a) * 2u,
             &Ah[(size_t)gr2 * 256 + k0 + c8_a]);
        cp16(aBase + (uint32_t)((r_a + 64) * KP2 + c8_a) * 2u,
             &Ah[(size_t)gr2b * 256 + k0 + c8_a]);
        cp16(bBase + (uint32_t)(r_a * KP2 + c8_a) * 2u,
             &Wt[(size_t)(colBase + r_a) * 256 + k0 + c8_a]);
        cp16(bBase + (uint32_t)((r_a + 64) * KP2 + c8_a) * 2u,
             &Wt[(size_t)(colBase + r_a + 64) * 256 + k0 + c8_a]);
        asm volatile("cp.async.commit_group;\n" ::: "memory");
    };

    float acc[2][8][4] = {};

    int lm  = lane >> 3;           // ldmatrix matrix index 0..3
    int lr  = lane & 7;            // row within matrix

    // prologue: stages 0..2 in flight
    load_stage(0, 0);
    load_stage(1, 1);
    load_stage(2, 2);

#pragma unroll
    for (int t = 0; t < 8; t++) {
        if (t <= 5)      asm volatile("cp.async.wait_group 2;\n" ::: "memory");
        else if (t == 6) asm volatile("cp.async.wait_group 1;\n" ::: "memory");
        else             asm volatile("cp.async.wait_group 0;\n" ::: "memory");
        __syncthreads();
        if (t + 3 < 8) load_stage((t + 3) % NSTG, t + 3);

        int st = t % NSTG;
        uint32_t aBase = smBase + (uint32_t)(st * 2 * STG_H) * 2u;
        uint32_t bBase = aBase + (uint32_t)STG_H * 2u;
        int k0 = t * 32;

#pragma unroll
        for (int ks = 0; ks < 2; ks++) {
            int kk = ks * 16;
            uint32_t a[2][4];
#pragma unroll
            for (int im = 0; im < 2; im++) {
                int row = mb + im * 16 + (lane & 15);
                int col = kk + ((lane >> 4) << 3);
                uint32_t addr = aBase + (uint32_t)(row * KP2 + col) * 2u;
                asm volatile(
                    "ldmatrix.sync.aligned.m8n8.x4.shared.b16 {%0,%1,%2,%3}, [%4];"
                    : "=r"(a[im][0]), "=r"(a[im][1]), "=r"(a[im][2]), "=r"(a[im][3])
                    : "r"(addr));
            }
            if (FUSE_BN) {
                int kb = k0 + kk + tg * 2;
                float2 sA = *(const float2*)&g_ss[kb];
                float2 hA = *(const float2*)&g_ss[256 + kb];
                float2 sB = *(const float2*)&g_ss[kb + 8];
                float2 hB = *(const float2*)&g_ss[256 + kb + 8];
#pragma unroll
                for (int im = 0; im < 2; im++) {
                    a[im][0] = bnfrag(a[im][0], sA, hA);
                    a[im][1] = bnfrag(a[im][1], sA, hA);
                    a[im][2] = bnfrag(a[im][2], sB, hB);
                    a[im][3] = bnfrag(a[im][3], sB, hB);
                }
            }
            uint32_t bf[8][2];
#pragma unroll
            for (int ntp = 0; ntp < 4; ntp++) {
                int row_n = nb + ntp * 16 + ((lm >> 1) << 3) + lr;
                int col   = kk + ((lm & 1) << 3);
                uint32_t addr = bBase + (uint32_t)(row_n * KP2 + col) * 2u;
                asm volatile(
                    "ldmatrix.sync.aligned.m8n8.x4.shared.b16 {%0,%1,%2,%3}, [%4];"
                    : "=r"(bf[ntp * 2][0]),     "=r"(bf[ntp * 2][1]),
                      "=r"(bf[ntp * 2 + 1][0]), "=r"(bf[ntp * 2 + 1][1])
                    : "r"(addr));
            }
#pragma unroll
            for (int nt = 0; nt < 8; nt++) {
                mma_f16(acc[0][nt], a[0], bf[nt][0], bf[nt][1]);
                mma_f16(acc[1][nt], a[1], bf[nt][0], bf[nt][1]);
            }
        }
    }

    // ---- epilogue ----
#pragma unroll
    for (int im = 0; im < 2; im++) {
#pragma unroll
        for (int nt = 0; nt < 8; nt++) {
            int row0 = rowBase + mb + im * 16 + g;
            int col  = colBase + nb + nt * 8 + tg * 2;
            float bx = 0.f, by = 0.f;
            if (bias) { bx = bias[col]; by = bias[col + 1]; }
#pragma unroll
            for (int h = 0; h < 2; h++) {
                int row = row0 + h * 8;
                if (row < M) {
                    float ox = acc[im][nt][h * 2 + 0] + bx;
                    float oy = acc[im][nt][h * 2 + 1] + by;
                    if (OUT16) {
                        *(__half2*)&Ch[(size_t)row * 256 + col] =
                            __floats2half2_rn(ox, oy);
                    } else {
                        if (col < 128)
                            *(float2*)&Cf[(size_t)row * 128 + col] =
                                make_float2(ox, oy);
                        else
                            *(float2*)&Cf[(size_t)NN * 128 + (size_t)row * 128 + (col - 128)] =
                                make_float2(ox, oy);
                    }
                }
            }
        }
    }
}

// ---------------- CSR aggregation, MLP=4, + fused BN stats ----------------
__device__ __forceinline__ void fma8(float* acc, uint4 r, float c) {
    __half2* hp = (__half2*)&r;
#pragma unroll
    for (int q = 0; q < 4; q++) {
        float2 p = __half22float2(hp[q]);
        acc[q * 2]     += c * p.x;
        acc[q * 2 + 1] += c * p.y;
    }
}

__global__ void k_agg_csr(const __half* __restrict__ h, __half* __restrict__ out,
                          const float* __restrict__ bias) {
    __shared__ float s_sum[8][256];
    __shared__ float s_sq [8][256];

    int grp  = threadIdx.x >> 5;     // 0..7
    int lane = threadIdx.x & 31;
    int node = blockIdx.x * 8 + grp;
    int f = lane * 8;

    float acc[8] = {};
    if (node < NN) {
        float di = g_dinv[node];
        float cs = di * di;
#pragma unroll
        for (int q = 0; q < 8; q++) acc[q] = bias[f + q];
        fma8(acc, *(const uint4*)&h[(size_t)node * 256 + f], cs);

        int beg = g_ptr[node];
        int end = beg + g_cnt[node];
        int2 rec = make_int2(0, 0);
        if (lane < 4 && beg + lane < end) rec = g_csr[beg + lane];

        for (int j = beg; j < end; j += 4) {
            int2 cur = rec;
            int jn = j + 4;
            int2 nx = make_int2(0, 0);
            if (lane < 4 && jn + lane < end) nx = g_csr[jn + lane];
            rec = nx;
            int take = end - j;      // warp-uniform

            int   s0 = __shfl_sync(0xffffffffu, cur.x, 0);
            float c0 = __int_as_float(__shfl_sync(0xffffffffu, cur.y, 0));
            int   s1 = __shfl_sync(0xffffffffu, cur.x, 1);
            float c1 = __int_as_float(__shfl_sync(0xffffffffu, cur.y, 1));
            int   s2 = __shfl_sync(0xffffffffu, cur.x, 2);
            float c2 = __int_as_float(__shfl_sync(0xffffffffu, cur.y, 2));
            int   s3 = __shfl_sync(0xffffffffu, cur.x, 3);
            float c3 = __int_as_float(__shfl_sync(0xffffffffu, cur.y, 3));

            uint4 r0 = *(const uint4*)&h[(size_t)s0 * 256 + f];
            if (take > 1) {
                uint4 r1 = *(const uint4*)&h[(size_t)s1 * 256 + f];
                if (take > 2) {
                    uint4 r2 = *(const uint4*)&h[(size_t)s2 * 256 + f];
                    if (take > 3) {
                        uint4 r3 = *(const uint4*)&h[(size_t)s3 * 256 + f];
                        fma8(acc, r3, c3);
                    }
                    fma8(acc, r2, c2);
                }
                fma8(acc, r1, c1);
            }
            fma8(acc, r0, c0);
        }

        __half2 o0 = __floats2half2_rn(acc[0], acc[1]);
        __half2 o1 = __floats2half2_rn(acc[2], acc[3]);
        __half2 o2 = __floats2half2_rn(acc[4], acc[5]);
        __half2 o3 = __floats2half2_rn(acc[6], acc[7]);
        uint4 ov = make_uint4(*(uint32_t*)&o0, *(uint32_t*)&o1,
                              *(uint32_t*)&o2, *(uint32_t*)&o3);
        *(uint4*)&out[(size_t)node * 256 + f] = ov;
    }

#pragma unroll
    for (int q = 0; q < 8; q++) {
        s_sum[grp][f + q] = acc[q];
        s_sq [grp][f + q] = acc[q] * acc[q];
    }
    __syncthreads();

    int t = threadIdx.x;   // feature
    float s = 0.f, q = 0.f;
#pragma unroll
    for (int gi = 0; gi < 8; gi++) { s += s_sum[gi][t]; q += s_sq[gi][t]; }
    atomicAdd(&g_stats[t], s);
    atomicAdd(&g_stats[HDIM + t], q);
}

__global__ void k_bn_final(const float* __restrict__ gamma, const float* __restrict__ beta) {
    int f = threadIdx.x;
    float inv_n = 1.0f / (float)NN;
    float m  = g_stats[f] * inv_n;
    float v  = g_stats[HDIM + f] * inv_n - m * m;
    float sc = gamma[f] * rsqrtf(v + BN_EPS);
    g_ss[f]        = sc;
    g_ss[HDIM + f] = beta[f] - m * sc;
    g_stats[f] = 0.0f;
    g_stats[HDIM + f] = 0.0f;
}

// ---------------- launch ----------------
extern "C" void kernel_launch(void* const* d_in, const int* in_sizes, int n_in,
                              void* d_out, int out_size) {
    const float* x   = (const float*)d_in[0];
    const int*   ei  = (const int*)  d_in[1];   // [2, E]: src then dst
    const float* W0  = (const float*)d_in[2];
    const float* b0  = (const float*)d_in[3];
    const float* g0  = (const float*)d_in[4];
    const float* be0 = (const float*)d_in[5];
    const float* W1  = (const float*)d_in[6];
    const float* b1  = (const float*)d_in[7];
    const float* g1  = (const float*)d_in[8];
    const float* be1 = (const float*)d_in[9];
    const float* Wmu = (const float*)d_in[10];
    const float* bmu = (const float*)d_in[11];
    const float* Wlv = (const float*)d_in[12];
    const float* blv = (const float*)d_in[13];
    float* out = (float*)d_out;

    const int* src = ei;
    const int* dst = ei + EE;

    __half *h16 = nullptr, *a16 = nullptr, *w0t = nullptr, *w1t = nullptr, *wct = nullptr;
    float  *bcat = nullptr;
    cudaGetSymbolAddress((void**)&h16,  g_h16);
    cudaGetSymbolAddress((void**)&a16,  g_a16);
    cudaGetSymbolAddress((void**)&w0t,  g_w0t);
    cudaGetSymbolAddress((void**)&w1t,  g_w1t);
    cudaGetSymbolAddress((void**)&wct,  g_wct);
    cudaGetSymbolAddress((void**)&bcat, g_bcat);

    // side stream + fork/join events (created once, outside any capture)
    static cudaStream_t s2 = nullptr;
    static cudaEvent_t  evF = nullptr, evJ = nullptr;
    if (!s2) {
        cudaStreamCreateWithFlags(&s2, cudaStreamNonBlocking);
        cudaEventCreateWithFlags(&evF, cudaEventDisableTiming);
        cudaEventCreateWithFlags(&evJ, cudaEventDisableTiming);
    }

    const int NB_N  = SCAN_B;
    const int NB_E  = (EE + 255) / 256;
    const int NB_AG = (NN + 7) / 8;             // 6250
    const int NB_DW = SCAN_B + 768 + 6250;
    const dim3 G_GEMM((NN + 127) / 128, 2);     // 391 x 2

    const int SMEM = NSTG * 2 * STG_H * 2;      // 81920 bytes
    cudaFuncSetAttribute(gemm_ca<false, true>,
                         cudaFuncAttributeMaxDynamicSharedMemorySize, SMEM);
    cudaFuncSetAttribute(gemm_ca<true, true>,
                         cudaFuncAttributeMaxDynamicSharedMemorySize, SMEM);
    cudaFuncSetAttribute(gemm_ca<true, false>,
                         cudaFuncAttributeMaxDynamicSharedMemorySize, SMEM);

    // 1-3: counts, dinv + weight cvt + x -> fp16 (into a16)
    k_cnt_zero  <<<NB_N, 256>>>();
    k_cnt       <<<NB_E, 256>>>(dst);
    k_dinv_wcvt <<<NB_DW, 256>>>(x, W0, W1, Wmu, Wlv, bmu, blv);

    // fork: CSR build on side stream, concurrent with layer-0 GEMM
    cudaEventRecord(evF, 0);
    cudaStreamWaitEvent(s2, evF, 0);
    k_ptra<<<NB_N, 256, 0, s2>>>();
    k_fill<<<NB_E, 256, 0, s2>>>(src, dst);
    cudaEventRecord(evJ, s2);

    // layer-0 hidden GEMM (default stream, overlaps with CSR build)
    gemm_ca<false, true><<<G_GEMM, 256, SMEM>>>(a16, w0t, nullptr, nullptr, h16, NN);

    // join
    cudaStreamWaitEvent(0, evJ, 0);

    // layer 0 aggregation + BN coeffs
    k_agg_csr <<<NB_AG, 256>>>(h16, a16, b0);
    k_bn_final<<<1, 256>>>(g0, be0);

    // layer 1
    gemm_ca<true, true><<<G_GEMM, 256, SMEM>>>(a16, w1t, nullptr, nullptr, h16, NN);
    k_agg_csr <<<NB_AG, 256>>>(h16, a16, b1);
    k_bn_final<<<1, 256>>>(g1, be1);

    // heads: combined mu|logvar GEMM with split epilogue
    gemm_ca<true, false><<<G_GEMM, 256, SMEM>>>(a16, wct, bcat, out, nullptr, NN);
}